// round 8
// baseline (speedup 1.0000x reference)
#include <cuda_runtime.h>
#include <cuda_bf16.h>
#include <cstdint>

// ---------------------------------------------------------------------------
// HydraAttention: B=8, L=4096, dim=1024, n_heads=8, d_head=128, d=16
// Round 8: fused-split bf16 3-term GEMM; mma stream reordered into three
//          RAW-free passes (acc reuse distance 2 -> 24 mmas)
// ---------------------------------------------------------------------------

static constexpr int Bb  = 8;
static constexpr int Ll  = 4096;
static constexpr int DIM = 1024;
static constexpr int DH  = 128;
static constexpr int NH  = 8;
static constexpr int Dd  = 16;
static constexpr int MTOK = Bb * Ll;      // 32768

__device__ float g_qkv[3][MTOK * DH];     // 48 MB scratch
__device__ float g_kvpart[Bb * NH][4][Dd];

// ---------------- PTX helpers ----------------------------------------------
__device__ __forceinline__ uint32_t smem_u32(const void* p) {
    uint32_t a;
    asm("{ .reg .u64 t; cvta.to.shared.u64 t, %1; cvt.u32.u64 %0, t; }"
        : "=r"(a) : "l"(p));
    return a;
}
__device__ __forceinline__ void ldsm4(uint32_t* r, uint32_t a) {
    asm volatile("ldmatrix.sync.aligned.m8n8.x4.shared.b16 {%0,%1,%2,%3}, [%4];"
        : "=r"(r[0]), "=r"(r[1]), "=r"(r[2]), "=r"(r[3]) : "r"(a));
}
__device__ __forceinline__ void mma_bf16(float* c, const uint32_t* a, const uint32_t* b) {
    asm volatile(
        "mma.sync.aligned.m16n8k16.row.col.f32.bf16.bf16.f32 "
        "{%0,%1,%2,%3}, {%4,%5,%6,%7}, {%8,%9}, {%0,%1,%2,%3};"
        : "+f"(c[0]), "+f"(c[1]), "+f"(c[2]), "+f"(c[3])
        : "r"(a[0]), "r"(a[1]), "r"(a[2]), "r"(a[3]), "r"(b[0]), "r"(b[1]));
}

// Conflict-free swizzle for 64B rows.
__device__ __forceinline__ uint32_t swz(int row, int c16) {
    return (uint32_t)(row * 64 + ((c16 ^ ((row >> 1) & 3)) << 4));
}

// ---------------- Kernel 1: fused-split QKV GEMM ---------------------------
// grid = (2, 256): N-half x M-block. Stage (40KB):
//   Ah[128x32] @0, Al @8192, Bh[192x32] @16384, Bl @28672 ; 3 stages = 120KB
static constexpr uint32_t STAGE = 40960;
static constexpr uint32_t GEMM_SMEM = 3 * STAGE;   // 122880
static constexpr int NCH = 32;                     // K chunks of 32

__global__ __launch_bounds__(256) void qkv_gemm_fused(
    const float* __restrict__ X,
    const float* __restrict__ Wq, const float* __restrict__ bq,
    const float* __restrict__ Wk, const float* __restrict__ bk,
    const float* __restrict__ Wv, const float* __restrict__ bv)
{
    extern __shared__ __align__(128) unsigned char smem[];
    const uint32_t sbase = smem_u32(smem);
    const int tid = threadIdx.x, lid = tid & 31, wid = tid >> 5;
    const int nb = blockIdx.x;            // 0/1 -> QKV cols [nb*192, nb*192+192)
    const int bm = blockIdx.y * 128;
    const int wm = (wid >> 1) * 32;       // warp M offset
    const int wn = (wid & 1) * 96;        // warp N offset (within 192)

    float acc[2][12][4];
#pragma unroll
    for (int i = 0; i < 2; i++)
#pragma unroll
        for (int j = 0; j < 12; j++)
#pragma unroll
            for (int k = 0; k < 4; k++) acc[i][j][k] = 0.f;

    float4 areg[4];
    float4 breg[6];

    auto ldgA = [&](int kc) {
#pragma unroll
        for (int u = 0; u < 2; u++) {
            const int id = tid + 256 * u;
            const int row = id >> 2, c16 = id & 3;
            const float* p = X + (size_t)(bm + row) * DIM + kc * 32 + c16 * 8;
            areg[2*u]   = *(const float4*)p;
            areg[2*u+1] = *(const float4*)(p + 4);
        }
    };
    auto ldgB = [&](int kc) {
#pragma unroll
        for (int u = 0; u < 3; u++) {
            const int id = tid + 256 * u;
            const int row = id >> 2, c16 = id & 3;
            const int rg = nb * 192 + row;
            const int mat = rg >> 7;
            const float* W = (mat == 0) ? Wq : (mat == 1) ? Wk : Wv;
            const float* p = W + (size_t)(rg & 127) * DIM + kc * 32 + c16 * 8;
            breg[2*u]   = *(const float4*)p;
            breg[2*u+1] = *(const float4*)(p + 4);
        }
    };
    auto cvt8 = [&](const float4& a, const float4& b, uint4& hi4, uint4& lo4) {
        float xs[8] = {a.x, a.y, a.z, a.w, b.x, b.y, b.z, b.w};
        __align__(16) __nv_bfloat16 hi[8];
        __align__(16) __nv_bfloat16 lo[8];
#pragma unroll
        for (int i = 0; i < 8; i++) {
            hi[i] = __float2bfloat16(xs[i]);
            lo[i] = __float2bfloat16(xs[i] - __bfloat162float(hi[i]));
        }
        hi4 = *(const uint4*)hi;
        lo4 = *(const uint4*)lo;
    };
    auto stage_sts = [&](int s) {
        const uint32_t st = (uint32_t)s * STAGE;
#pragma unroll
        for (int u = 0; u < 2; u++) {
            const int id = tid + 256 * u;
            const int row = id >> 2, c16 = id & 3;
            const uint32_t off = st + swz(row, c16);
            uint4 hi4, lo4;
            cvt8(areg[2*u], areg[2*u+1], hi4, lo4);
            *(uint4*)(smem + off)        = hi4;
            *(uint4*)(smem + off + 8192) = lo4;
        }
#pragma unroll
        for (int u = 0; u < 3; u++) {
            const int id = tid + 256 * u;
            const int row = id >> 2, c16 = id & 3;
            const uint32_t off = st + 16384 + swz(row, c16);
            uint4 hi4, lo4;
            cvt8(breg[2*u], breg[2*u+1], hi4, lo4);
            *(uint4*)(smem + off)         = hi4;
            *(uint4*)(smem + off + 12288) = lo4;
        }
    };

    // prologue
    ldgA(0); ldgB(0); stage_sts(0);
    ldgA(1); ldgB(1); stage_sts(1);
    ldgA(2); ldgB(2);
    __syncthreads();

    for (int c = 0; c < NCH; c++) {
        if (c + 2 < NCH) {
            stage_sts((c + 2) % 3);
            if (c + 3 < NCH) { ldgA(c + 3); ldgB(c + 3); }
        }

        const uint32_t st = sbase + (uint32_t)(c % 3) * STAGE;
#pragma unroll
        for (int ks = 0; ks < 2; ks++) {
            uint32_t ah[8], al[8], bb[24];
            // A fragments (hi & lo)
#pragma unroll
            for (int mt = 0; mt < 2; mt++) {
                const int row = wm + mt * 16 + (lid & 15);
                const int c16 = ks * 2 + (lid >> 4);
                const uint32_t off = st + swz(row, c16);
                ldsm4(ah + mt * 4, off);
                ldsm4(al + mt * 4, off + 8192);
            }
            // B hi fragments
#pragma unroll
            for (int np = 0; np < 6; np++) {
                const int row = wn + np * 16 + (lid & 7) + ((lid >> 4) << 3);
                const int c16 = ks * 2 + ((lid >> 3) & 1);
                const uint32_t off = st + 16384 + swz(row, c16);
                ldsm4(bb + np * 4, off);
            }
            // pass 1: Ah*Bh -- 24 mmas, all-distinct accumulators (no RAW)
#pragma unroll
            for (int mt = 0; mt < 2; mt++)
#pragma unroll
                for (int np = 0; np < 6; np++) {
                    mma_bf16(acc[mt][np*2],     ah + mt*4, bb + np*4);
                    mma_bf16(acc[mt][np*2 + 1], ah + mt*4, bb + np*4 + 2);
                }
            // pass 2: Al*Bh -- acc reuse distance 24 mmas
#pragma unroll
            for (int mt = 0; mt < 2; mt++)
#pragma unroll
                for (int np = 0; np < 6; np++) {
                    mma_bf16(acc[mt][np*2],     al + mt*4, bb + np*4);
                    mma_bf16(acc[mt][np*2 + 1], al + mt*4, bb + np*4 + 2);
                }
            // B lo fragments (reuse bb)
#pragma unroll
            for (int np = 0; np < 6; np++) {
                const int row = wn + np * 16 + (lid & 7) + ((lid >> 4) << 3);
                const int c16 = ks * 2 + ((lid >> 3) & 1);
                const uint32_t off = st + 28672 + swz(row, c16);
                ldsm4(bb + np * 4, off);
            }
            // pass 3: Ah*Bl
#pragma unroll
            for (int mt = 0; mt < 2; mt++)
#pragma unroll
                for (int np = 0; np < 6; np++) {
                    mma_bf16(acc[mt][np*2],     ah + mt*4, bb + np*4);
                    mma_bf16(acc[mt][np*2 + 1], ah + mt*4, bb + np*4 + 2);
                }
        }
        __syncthreads();
    }

    // epilogue: add bias, store fp32 into g_qkv[mat]
    const int tr = lid >> 2, tc = (lid & 3) * 2;
#pragma unroll
    for (int mt = 0; mt < 2; mt++)
#pragma unroll
        for (int n8 = 0; n8 < 12; n8++) {
            const int gn  = nb * 192 + wn + n8 * 8 + tc;
            const int mat = gn >> 7;
            const int col = gn & 127;
            const float* bias = (mat == 0) ? bq : (mat == 1) ? bk : bv;
            float* Cp = g_qkv[mat];
            const float b0 = bias[col], b1 = bias[col + 1];
            const int r0 = bm + wm + mt * 16 + tr;
            float2 v0 = {acc[mt][n8][0] + b0, acc[mt][n8][1] + b1};
            float2 v1 = {acc[mt][n8][2] + b0, acc[mt][n8][3] + b1};
            *(float2*)&Cp[(size_t)r0 * DH + col]       = v0;
            *(float2*)&Cp[(size_t)(r0 + 8) * DH + col] = v1;
        }
}

// ---------------- Kernel 2: kv partial reduction ---------------------------
__global__ __launch_bounds__(256) void kv_reduce() {
    const int bh    = blockIdx.x;
    const int chunk = blockIdx.y;
    const int b = bh >> 3, h = bh & 7;
    const float* __restrict__ K = g_qkv[1];
    const float* __restrict__ V = g_qkv[2];

    float acc[Dd];
#pragma unroll
    for (int d = 0; d < Dd; d++) acc[d] = 0.f;

    for (int l = chunk * 1024 + threadIdx.x; l < (chunk + 1) * 1024; l += 256) {
        const size_t base = (size_t)(b * Ll + l) * DH + h * Dd;
        float kx[Dd], vx[Dd];
        const float4* kp = (const float4*)(K + base);
        const float4* vp = (const float4*)(V + base);
#pragma unroll
        for (int q = 0; q < 4; q++) {
            float4 kv4 = kp[q];
            kx[q*4+0] = kv4.x; kx[q*4+1] = kv4.y; kx[q*4+2] = kv4.z; kx[q*4+3] = kv4.w;
            float4 vv4 = vp[q];
            vx[q*4+0] = vv4.x; vx[q*4+1] = vv4.y; vx[q*4+2] = vv4.z; vx[q*4+3] = vv4.w;
        }
        float ss = 0.f;
#pragma unroll
        for (int d = 0; d < Dd; d++) ss += kx[d] * kx[d];
        const float rn = rsqrtf(ss);
#pragma unroll
        for (int d = 0; d < Dd; d++) acc[d] += kx[d] * rn * vx[d];
    }

    __shared__ float red[256][17];
#pragma unroll
    for (int d = 0; d < Dd; d++) red[threadIdx.x][d] = acc[d];
    __syncthreads();
    for (int s = 128; s > 0; s >>= 1) {
        if (threadIdx.x < s) {
#pragma unroll
            for (int d = 0; d < Dd; d++)
                red[threadIdx.x][d] += red[threadIdx.x + s][d];
        }
        __syncthreads();
    }
    if (threadIdx.x < Dd)
        g_kvpart[bh][chunk][threadIdx.x] = red[0][threadIdx.x];
}

// ---------------- Kernel 3: q-normalize * kv, LayerNorm --------------------
__global__ __launch_bounds__(256) void finalize(
    const float* __restrict__ gamma, const float* __restrict__ beta,
    float* __restrict__ out)
{
    const int idx = blockIdx.x * blockDim.x + threadIdx.x;
    const int l = idx & (Ll - 1);
    const int h = (idx >> 12) & 7;
    const int b = idx >> 15;

    const size_t qbase = (size_t)(b * Ll + l) * DH + h * Dd;
    float q[Dd];
    const float4* qp = (const float4*)(g_qkv[0] + qbase);
#pragma unroll
    for (int g = 0; g < 4; g++) {
        float4 v = qp[g];
        q[g*4+0] = v.x; q[g*4+1] = v.y; q[g*4+2] = v.z; q[g*4+3] = v.w;
    }

    const int bh = (b << 3) | h;
    float kv[Dd];
#pragma unroll
    for (int d = 0; d < Dd; d++)
        kv[d] = g_kvpart[bh][0][d] + g_kvpart[bh][1][d]
              + g_kvpart[bh][2][d] + g_kvpart[bh][3][d];

    float ss = 0.f;
#pragma unroll
    for (int d = 0; d < Dd; d++) ss += q[d] * q[d];
    const float rn = rsqrtf(ss);

    float a[Dd];
    float mu = 0.f;
#pragma unroll
    for (int d = 0; d < Dd; d++) { a[d] = q[d] * rn * kv[d]; mu += a[d]; }
    mu *= (1.f / Dd);
    float var = 0.f;
#pragma unroll
    for (int d = 0; d < Dd; d++) { float t = a[d] - mu; var += t * t; }
    var *= (1.f / Dd);
    const float rs = rsqrtf(var + 1e-5f);

    float* op = out + (size_t)idx * Dd;
#pragma unroll
    for (int g = 0; g < 4; g++) {
        float4 o;
        o.x = (a[g*4+0] - mu) * rs * gamma[g*4+0] + beta[g*4+0];
        o.y = (a[g*4+1] - mu) * rs * gamma[g*4+1] + beta[g*4+1];
        o.z = (a[g*4+2] - mu) * rs * gamma[g*4+2] + beta[g*4+2];
        o.w = (a[g*4+3] - mu) * rs * gamma[g*4+3] + beta[g*4+3];
        *(float4*)&op[g * 4] = o;
    }
}

// ---------------------------------------------------------------------------
extern "C" void kernel_launch(void* const* d_in, const int* in_sizes, int n_in,
                              void* d_out, int out_size)
{
    (void)in_sizes; (void)n_in; (void)out_size;
    const float* x     = (const float*)d_in[0];
    const float* Wq    = (const float*)d_in[1];
    const float* bq    = (const float*)d_in[2];
    const float* Wk    = (const float*)d_in[3];
    const float* bk    = (const float*)d_in[4];
    const float* Wv    = (const float*)d_in[5];
    const float* bv    = (const float*)d_in[6];
    const float* gamma = (const float*)d_in[7];
    const float* beta  = (const float*)d_in[8];
    float* out = (float*)d_out;

    static bool attr_set = false;
    if (!attr_set) {
        cudaFuncSetAttribute(qkv_gemm_fused,
                             cudaFuncAttributeMaxDynamicSharedMemorySize, GEMM_SMEM);
        attr_set = true;
    }

    qkv_gemm_fused<<<dim3(2, 256), 256, GEMM_SMEM>>>(x, Wq, bq, Wk, bk, Wv, bv);
    kv_reduce<<<dim3(Bb * NH, 4), 256>>>();
    finalize<<<(Bb * NH * Ll) / 256, 256>>>(gamma, beta, out);
}

// round 9
// speedup vs baseline: 1.0961x; 1.0961x over previous
#include <cuda_runtime.h>
#include <cuda_bf16.h>
#include <cstdint>

// ---------------------------------------------------------------------------
// HydraAttention: B=8, L=4096, dim=1024, n_heads=8, d_head=128, d=16
// Round 9: fused-split bf16 3-term GEMM; 512 threads (16 warps, 4x4 grid,
//          warp tile 32x48) to double warps/SMSP and hide non-mma work
// ---------------------------------------------------------------------------

static constexpr int Bb  = 8;
static constexpr int Ll  = 4096;
static constexpr int DIM = 1024;
static constexpr int DH  = 128;
static constexpr int NH  = 8;
static constexpr int Dd  = 16;
static constexpr int MTOK = Bb * Ll;      // 32768

__device__ float g_qkv[3][MTOK * DH];     // 48 MB scratch
__device__ float g_kvpart[Bb * NH][4][Dd];

// ---------------- PTX helpers ----------------------------------------------
__device__ __forceinline__ uint32_t smem_u32(const void* p) {
    uint32_t a;
    asm("{ .reg .u64 t; cvta.to.shared.u64 t, %1; cvt.u32.u64 %0, t; }"
        : "=r"(a) : "l"(p));
    return a;
}
__device__ __forceinline__ void ldsm4(uint32_t* r, uint32_t a) {
    asm volatile("ldmatrix.sync.aligned.m8n8.x4.shared.b16 {%0,%1,%2,%3}, [%4];"
        : "=r"(r[0]), "=r"(r[1]), "=r"(r[2]), "=r"(r[3]) : "r"(a));
}
__device__ __forceinline__ void mma_bf16(float* c, const uint32_t* a, const uint32_t* b) {
    asm volatile(
        "mma.sync.aligned.m16n8k16.row.col.f32.bf16.bf16.f32 "
        "{%0,%1,%2,%3}, {%4,%5,%6,%7}, {%8,%9}, {%0,%1,%2,%3};"
        : "+f"(c[0]), "+f"(c[1]), "+f"(c[2]), "+f"(c[3])
        : "r"(a[0]), "r"(a[1]), "r"(a[2]), "r"(a[3]), "r"(b[0]), "r"(b[1]));
}

// Conflict-free swizzle for 64B rows.
__device__ __forceinline__ uint32_t swz(int row, int c16) {
    return (uint32_t)(row * 64 + ((c16 ^ ((row >> 1) & 3)) << 4));
}

// ---------------- Kernel 1: fused-split QKV GEMM ---------------------------
// grid = (2, 256): N-half x M-block. Stage (40KB):
//   Ah[128x32] @0, Al @8192, Bh[192x32] @16384, Bl @28672 ; 3 stages = 120KB
static constexpr uint32_t STAGE = 40960;
static constexpr uint32_t GEMM_SMEM = 3 * STAGE;   // 122880
static constexpr int NCH = 32;                     // K chunks of 32
static constexpr int NTHR = 512;

__global__ __launch_bounds__(NTHR, 1) void qkv_gemm_fused(
    const float* __restrict__ X,
    const float* __restrict__ Wq, const float* __restrict__ bq,
    const float* __restrict__ Wk, const float* __restrict__ bk,
    const float* __restrict__ Wv, const float* __restrict__ bv)
{
    extern __shared__ __align__(128) unsigned char smem[];
    const uint32_t sbase = smem_u32(smem);
    const int tid = threadIdx.x, lid = tid & 31, wid = tid >> 5;
    const int nb = blockIdx.x;            // 0/1 -> QKV cols [nb*192, nb*192+192)
    const int bm = blockIdx.y * 128;
    const int wm = (wid >> 2) * 32;       // warp M offset (4 M-warps)
    const int wn = (wid & 3) * 48;        // warp N offset (4 N-warps x 48)

    float acc[2][6][4];
#pragma unroll
    for (int i = 0; i < 2; i++)
#pragma unroll
        for (int j = 0; j < 6; j++)
#pragma unroll
            for (int k = 0; k < 4; k++) acc[i][j][k] = 0.f;

    float4 areg[2];   // A staging: 1 slot  (8 floats)
    float4 breg[4];   // B staging: 2 slots (predicated)

    // A tile: 128 rows x 4 slots = 512 slots -> exactly 1 per thread
    const int arow = tid >> 2, ac16 = tid & 3;
    // B tile: 192 rows x 4 slots = 768 slots -> 1 + (tid<256 ? 1 : 0)
    auto ldgA = [&](int kc) {
        const float* p = X + (size_t)(bm + arow) * DIM + kc * 32 + ac16 * 8;
        areg[0] = *(const float4*)p;
        areg[1] = *(const float4*)(p + 4);
    };
    auto ldgB = [&](int kc) {
#pragma unroll
        for (int u = 0; u < 2; u++) {
            const int id = tid + NTHR * u;
            if (id < 768) {
                const int row = id >> 2, c16 = id & 3;
                const int rg = nb * 192 + row;
                const int mat = rg >> 7;
                const float* W = (mat == 0) ? Wq : (mat == 1) ? Wk : Wv;
                const float* p = W + (size_t)(rg & 127) * DIM + kc * 32 + c16 * 8;
                breg[2*u]   = *(const float4*)p;
                breg[2*u+1] = *(const float4*)(p + 4);
            }
        }
    };
    auto cvt8 = [&](const float4& a, const float4& b, uint4& hi4, uint4& lo4) {
        float xs[8] = {a.x, a.y, a.z, a.w, b.x, b.y, b.z, b.w};
        __align__(16) __nv_bfloat16 hi[8];
        __align__(16) __nv_bfloat16 lo[8];
#pragma unroll
        for (int i = 0; i < 8; i++) {
            hi[i] = __float2bfloat16(xs[i]);
            lo[i] = __float2bfloat16(xs[i] - __bfloat162float(hi[i]));
        }
        hi4 = *(const uint4*)hi;
        lo4 = *(const uint4*)lo;
    };
    auto stage_sts = [&](int s) {
        const uint32_t st = (uint32_t)s * STAGE;
        {
            const uint32_t off = st + swz(arow, ac16);
            uint4 hi4, lo4;
            cvt8(areg[0], areg[1], hi4, lo4);
            *(uint4*)(smem + off)        = hi4;
            *(uint4*)(smem + off + 8192) = lo4;
        }
#pragma unroll
        for (int u = 0; u < 2; u++) {
            const int id = tid + NTHR * u;
            if (id < 768) {
                const int row = id >> 2, c16 = id & 3;
                const uint32_t off = st + 16384 + swz(row, c16);
                uint4 hi4, lo4;
                cvt8(breg[2*u], breg[2*u+1], hi4, lo4);
                *(uint4*)(smem + off)         = hi4;
                *(uint4*)(smem + off + 12288) = lo4;
            }
        }
    };

    // prologue
    ldgA(0); ldgB(0); stage_sts(0);
    ldgA(1); ldgB(1); stage_sts(1);
    ldgA(2); ldgB(2);
    __syncthreads();

    for (int c = 0; c < NCH; c++) {
        if (c + 2 < NCH) {
            stage_sts((c + 2) % 3);
            if (c + 3 < NCH) { ldgA(c + 3); ldgB(c + 3); }
        }

        const uint32_t st = sbase + (uint32_t)(c % 3) * STAGE;
#pragma unroll
        for (int ks = 0; ks < 2; ks++) {
            uint32_t ah[8], al[8], bb[12];
            // A fragments (hi & lo)
#pragma unroll
            for (int mt = 0; mt < 2; mt++) {
                const int row = wm + mt * 16 + (lid & 15);
                const int c16 = ks * 2 + (lid >> 4);
                const uint32_t off = st + swz(row, c16);
                ldsm4(ah + mt * 4, off);
                ldsm4(al + mt * 4, off + 8192);
            }
            // B hi fragments: 3 x4-ldmatrix cover 6 n8 tiles
#pragma unroll
            for (int np = 0; np < 3; np++) {
                const int row = wn + np * 16 + (lid & 7) + ((lid >> 4) << 3);
                const int c16 = ks * 2 + ((lid >> 3) & 1);
                const uint32_t off = st + 16384 + swz(row, c16);
                ldsm4(bb + np * 4, off);
            }
            // pass 1: Ah*Bh
#pragma unroll
            for (int mt = 0; mt < 2; mt++)
#pragma unroll
                for (int np = 0; np < 3; np++) {
                    mma_bf16(acc[mt][np*2],     ah + mt*4, bb + np*4);
                    mma_bf16(acc[mt][np*2 + 1], ah + mt*4, bb + np*4 + 2);
                }
            // pass 2: Al*Bh
#pragma unroll
            for (int mt = 0; mt < 2; mt++)
#pragma unroll
                for (int np = 0; np < 3; np++) {
                    mma_bf16(acc[mt][np*2],     al + mt*4, bb + np*4);
                    mma_bf16(acc[mt][np*2 + 1], al + mt*4, bb + np*4 + 2);
                }
            // B lo fragments (reuse bb)
#pragma unroll
            for (int np = 0; np < 3; np++) {
                const int row = wn + np * 16 + (lid & 7) + ((lid >> 4) << 3);
                const int c16 = ks * 2 + ((lid >> 3) & 1);
                const uint32_t off = st + 28672 + swz(row, c16);
                ldsm4(bb + np * 4, off);
            }
            // pass 3: Ah*Bl
#pragma unroll
            for (int mt = 0; mt < 2; mt++)
#pragma unroll
                for (int np = 0; np < 3; np++) {
                    mma_bf16(acc[mt][np*2],     ah + mt*4, bb + np*4);
                    mma_bf16(acc[mt][np*2 + 1], ah + mt*4, bb + np*4 + 2);
                }
        }
        __syncthreads();
    }

    // epilogue: add bias, store fp32 into g_qkv[mat]
    const int tr = lid >> 2, tc = (lid & 3) * 2;
#pragma unroll
    for (int mt = 0; mt < 2; mt++)
#pragma unroll
        for (int n8 = 0; n8 < 6; n8++) {
            const int gn  = nb * 192 + wn + n8 * 8 + tc;
            const int mat = gn >> 7;
            const int col = gn & 127;
            const float* bias = (mat == 0) ? bq : (mat == 1) ? bk : bv;
            float* Cp = g_qkv[mat];
            const float b0 = bias[col], b1 = bias[col + 1];
            const int r0 = bm + wm + mt * 16 + tr;
            float2 v0 = {acc[mt][n8][0] + b0, acc[mt][n8][1] + b1};
            float2 v1 = {acc[mt][n8][2] + b0, acc[mt][n8][3] + b1};
            *(float2*)&Cp[(size_t)r0 * DH + col]       = v0;
            *(float2*)&Cp[(size_t)(r0 + 8) * DH + col] = v1;
        }
}

// ---------------- Kernel 2: kv partial reduction ---------------------------
__global__ __launch_bounds__(256) void kv_reduce() {
    const int bh    = blockIdx.x;
    const int chunk = blockIdx.y;
    const int b = bh >> 3, h = bh & 7;
    const float* __restrict__ K = g_qkv[1];
    const float* __restrict__ V = g_qkv[2];

    float acc[Dd];
#pragma unroll
    for (int d = 0; d < Dd; d++) acc[d] = 0.f;

    for (int l = chunk * 1024 + threadIdx.x; l < (chunk + 1) * 1024; l += 256) {
        const size_t base = (size_t)(b * Ll + l) * DH + h * Dd;
        float kx[Dd], vx[Dd];
        const float4* kp = (const float4*)(K + base);
        const float4* vp = (const float4*)(V + base);
#pragma unroll
        for (int q = 0; q < 4; q++) {
            float4 kv4 = kp[q];
            kx[q*4+0] = kv4.x; kx[q*4+1] = kv4.y; kx[q*4+2] = kv4.z; kx[q*4+3] = kv4.w;
            float4 vv4 = vp[q];
            vx[q*4+0] = vv4.x; vx[q*4+1] = vv4.y; vx[q*4+2] = vv4.z; vx[q*4+3] = vv4.w;
        }
        float ss = 0.f;
#pragma unroll
        for (int d = 0; d < Dd; d++) ss += kx[d] * kx[d];
        const float rn = rsqrtf(ss);
#pragma unroll
        for (int d = 0; d < Dd; d++) acc[d] += kx[d] * rn * vx[d];
    }

    __shared__ float red[256][17];
#pragma unroll
    for (int d = 0; d < Dd; d++) red[threadIdx.x][d] = acc[d];
    __syncthreads();
    for (int s = 128; s > 0; s >>= 1) {
        if (threadIdx.x < s) {
#pragma unroll
            for (int d = 0; d < Dd; d++)
                red[threadIdx.x][d] += red[threadIdx.x + s][d];
        }
        __syncthreads();
    }
    if (threadIdx.x < Dd)
        g_kvpart[bh][chunk][threadIdx.x] = red[0][threadIdx.x];
}

// ---------------- Kernel 3: q-normalize * kv, LayerNorm --------------------
__global__ __launch_bounds__(256) void finalize(
    const float* __restrict__ gamma, const float* __restrict__ beta,
    float* __restrict__ out)
{
    const int idx = blockIdx.x * blockDim.x + threadIdx.x;
    const int l = idx & (Ll - 1);
    const int h = (idx >> 12) & 7;
    const int b = idx >> 15;

    const size_t qbase = (size_t)(b * Ll + l) * DH + h * Dd;
    float q[Dd];
    const float4* qp = (const float4*)(g_qkv[0] + qbase);
#pragma unroll
    for (int g = 0; g < 4; g++) {
        float4 v = qp[g];
        q[g*4+0] = v.x; q[g*4+1] = v.y; q[g*4+2] = v.z; q[g*4+3] = v.w;
    }

    const int bh = (b << 3) | h;
    float kv[Dd];
#pragma unroll
    for (int d = 0; d < Dd; d++)
        kv[d] = g_kvpart[bh][0][d] + g_kvpart[bh][1][d]
              + g_kvpart[bh][2][d] + g_kvpart[bh][3][d];

    float ss = 0.f;
#pragma unroll
    for (int d = 0; d < Dd; d++) ss += q[d] * q[d];
    const float rn = rsqrtf(ss);

    float a[Dd];
    float mu = 0.f;
#pragma unroll
    for (int d = 0; d < Dd; d++) { a[d] = q[d] * rn * kv[d]; mu += a[d]; }
    mu *= (1.f / Dd);
    float var = 0.f;
#pragma unroll
    for (int d = 0; d < Dd; d++) { float t = a[d] - mu; var += t * t; }
    var *= (1.f / Dd);
    const float rs = rsqrtf(var + 1e-5f);

    float* op = out + (size_t)idx * Dd;
#pragma unroll
    for (int g = 0; g < 4; g++) {
        float4 o;
        o.x = (a[g*4+0] - mu) * rs * gamma[g*4+0] + beta[g*4+0];
        o.y = (a[g*4+1] - mu) * rs * gamma[g*4+1] + beta[g*4+1];
        o.z = (a[g*4+2] - mu) * rs * gamma[g*4+2] + beta[g*4+2];
        o.w = (a[g*4+3] - mu) * rs * gamma[g*4+3] + beta[g*4+3];
        *(float4*)&op[g * 4] = o;
    }
}

// ---------------------------------------------------------------------------
extern "C" void kernel_launch(void* const* d_in, const int* in_sizes, int n_in,
                              void* d_out, int out_size)
{
    (void)in_sizes; (void)n_in; (void)out_size;
    const float* x     = (const float*)d_in[0];
    const float* Wq    = (const float*)d_in[1];
    const float* bq    = (const float*)d_in[2];
    const float* Wk    = (const float*)d_in[3];
    const float* bk    = (const float*)d_in[4];
    const float* Wv    = (const float*)d_in[5];
    const float* bv    = (const float*)d_in[6];
    const float* gamma = (const float*)d_in[7];
    const float* beta  = (const float*)d_in[8];
    float* out = (float*)d_out;

    static bool attr_set = false;
    if (!attr_set) {
        cudaFuncSetAttribute(qkv_gemm_fused,
                             cudaFuncAttributeMaxDynamicSharedMemorySize, GEMM_SMEM);
        attr_set = true;
    }

    qkv_gemm_fused<<<dim3(2, 256), NTHR, GEMM_SMEM>>>(x, Wq, bq, Wk, bk, Wv, bv);
    kv_reduce<<<dim3(Bb * NH, 4), 256>>>();
    finalize<<<(Bb * NH * Ll) / 256, 256>>>(gamma, beta, out);
}

// round 11
// speedup vs baseline: 1.9246x; 1.7559x over previous
#include <cuda_runtime.h>
#include <cuda_fp16.h>
#include <cstdint>

// ---------------------------------------------------------------------------
// HydraAttention: B=8, L=4096, dim=1024, n_heads=8, d_head=128, d=16
// Round 10: single-term fp16 GEMM (3x less tensor work than bf16 3-term).
//   Error model predicts rel_err ~3e-4 (< 1e-3 gate). If it fails, revert R9.
// ---------------------------------------------------------------------------

static constexpr int Bb  = 8;
static constexpr int Ll  = 4096;
static constexpr int DIM = 1024;
static constexpr int DH  = 128;
static constexpr int NH  = 8;
static constexpr int Dd  = 16;
static constexpr int MTOK = Bb * Ll;      // 32768

__device__ float g_qkv[3][MTOK * DH];     // 48 MB scratch
__device__ float g_kvpart[Bb * NH][4][Dd];

// ---------------- PTX helpers ----------------------------------------------
__device__ __forceinline__ uint32_t smem_u32(const void* p) {
    uint32_t a;
    asm("{ .reg .u64 t; cvta.to.shared.u64 t, %1; cvt.u32.u64 %0, t; }"
        : "=r"(a) : "l"(p));
    return a;
}
__device__ __forceinline__ void ldsm4(uint32_t* r, uint32_t a) {
    asm volatile("ldmatrix.sync.aligned.m8n8.x4.shared.b16 {%0,%1,%2,%3}, [%4];"
        : "=r"(r[0]), "=r"(r[1]), "=r"(r[2]), "=r"(r[3]) : "r"(a));
}
__device__ __forceinline__ void mma_f16(float* c, const uint32_t* a, const uint32_t* b) {
    asm volatile(
        "mma.sync.aligned.m16n8k16.row.col.f32.f16.f16.f32 "
        "{%0,%1,%2,%3}, {%4,%5,%6,%7}, {%8,%9}, {%0,%1,%2,%3};"
        : "+f"(c[0]), "+f"(c[1]), "+f"(c[2]), "+f"(c[3])
        : "r"(a[0]), "r"(a[1]), "r"(a[2]), "r"(a[3]), "r"(b[0]), "r"(b[1]));
}

// Conflict-free swizzle for 64B rows.
__device__ __forceinline__ uint32_t swz(int row, int c16) {
    return (uint32_t)(row * 64 + ((c16 ^ ((row >> 1) & 3)) << 4));
}

// ---------------- Kernel 1: fused fp16 QKV GEMM ----------------------------
// grid = (2, 256): N-half x M-block. Stage (20KB):
//   A[128x32 fp16] @0 (8KB), B[192x32 fp16] @8192 (12KB); 3 stages = 60KB
static constexpr uint32_t STAGE = 20480;
static constexpr uint32_t GEMM_SMEM = 3 * STAGE;   // 61440
static constexpr int NCH = 32;                     // K chunks of 32
static constexpr int NTHR = 512;

__global__ __launch_bounds__(NTHR, 1) void qkv_gemm_fused(
    const float* __restrict__ X,
    const float* __restrict__ Wq, const float* __restrict__ bq,
    const float* __restrict__ Wk, const float* __restrict__ bk,
    const float* __restrict__ Wv, const float* __restrict__ bv)
{
    extern __shared__ __align__(128) unsigned char smem[];
    const uint32_t sbase = smem_u32(smem);
    const int tid = threadIdx.x, lid = tid & 31, wid = tid >> 5;
    const int nb = blockIdx.x;            // 0/1 -> QKV cols [nb*192, nb*192+192)
    const int bm = blockIdx.y * 128;
    const int wm = (wid >> 2) * 32;       // warp M offset (4 M-warps)
    const int wn = (wid & 3) * 48;        // warp N offset (4 N-warps x 48)

    float acc[2][6][4];
#pragma unroll
    for (int i = 0; i < 2; i++)
#pragma unroll
        for (int j = 0; j < 6; j++)
#pragma unroll
            for (int k = 0; k < 4; k++) acc[i][j][k] = 0.f;

    float4 areg[2];   // A staging: 1 slot (8 floats)
    float4 breg[4];   // B staging: 2 slots (predicated)

    // A tile: 128 rows x 4 slots = 512 slots -> 1 per thread
    const int arow = tid >> 2, ac16 = tid & 3;
    auto ldgA = [&](int kc) {
        const float* p = X + (size_t)(bm + arow) * DIM + kc * 32 + ac16 * 8;
        areg[0] = *(const float4*)p;
        areg[1] = *(const float4*)(p + 4);
    };
    auto ldgB = [&](int kc) {
#pragma unroll
        for (int u = 0; u < 2; u++) {
            const int id = tid + NTHR * u;
            if (id < 768) {
                const int row = id >> 2, c16 = id & 3;
                const int rg = nb * 192 + row;
                const int mat = rg >> 7;
                const float* W = (mat == 0) ? Wq : (mat == 1) ? Wk : Wv;
                const float* p = W + (size_t)(rg & 127) * DIM + kc * 32 + c16 * 8;
                breg[2*u]   = *(const float4*)p;
                breg[2*u+1] = *(const float4*)(p + 4);
            }
        }
    };
    auto cvt8 = [&](const float4& a, const float4& b) -> uint4 {
        __align__(16) __half h[8];
        h[0] = __float2half_rn(a.x); h[1] = __float2half_rn(a.y);
        h[2] = __float2half_rn(a.z); h[3] = __float2half_rn(a.w);
        h[4] = __float2half_rn(b.x); h[5] = __float2half_rn(b.y);
        h[6] = __float2half_rn(b.z); h[7] = __float2half_rn(b.w);
        return *(const uint4*)h;
    };
    auto stage_sts = [&](int s) {
        const uint32_t st = (uint32_t)s * STAGE;
        *(uint4*)(smem + st + swz(arow, ac16)) = cvt8(areg[0], areg[1]);
#pragma unroll
        for (int u = 0; u < 2; u++) {
            const int id = tid + NTHR * u;
            if (id < 768) {
                const int row = id >> 2, c16 = id & 3;
                *(uint4*)(smem + st + 8192 + swz(row, c16))
                    = cvt8(breg[2*u], breg[2*u+1]);
            }
        }
    };

    // prologue
    ldgA(0); ldgB(0); stage_sts(0);
    ldgA(1); ldgB(1); stage_sts(1);
    ldgA(2); ldgB(2);
    __syncthreads();

    for (int c = 0; c < NCH; c++) {
        if (c + 2 < NCH) {
            stage_sts((c + 2) % 3);
            if (c + 3 < NCH) { ldgA(c + 3); ldgB(c + 3); }
        }

        const uint32_t st = sbase + (uint32_t)(c % 3) * STAGE;
#pragma unroll
        for (int ks = 0; ks < 2; ks++) {
            uint32_t ah[8], bb[12];
#pragma unroll
            for (int mt = 0; mt < 2; mt++) {
                const int row = wm + mt * 16 + (lid & 15);
                const int c16 = ks * 2 + (lid >> 4);
                ldsm4(ah + mt * 4, st + swz(row, c16));
            }
#pragma unroll
            for (int np = 0; np < 3; np++) {
                const int row = wn + np * 16 + (lid & 7) + ((lid >> 4) << 3);
                const int c16 = ks * 2 + ((lid >> 3) & 1);
                ldsm4(bb + np * 4, st + 8192 + swz(row, c16));
            }
#pragma unroll
            for (int mt = 0; mt < 2; mt++)
#pragma unroll
                for (int np = 0; np < 3; np++) {
                    mma_f16(acc[mt][np*2],     ah + mt*4, bb + np*4);
                    mma_f16(acc[mt][np*2 + 1], ah + mt*4, bb + np*4 + 2);
                }
        }
        __syncthreads();
    }

    // epilogue: add bias, store fp32 into g_qkv[mat]
    const int tr = lid >> 2, tc = (lid & 3) * 2;
#pragma unroll
    for (int mt = 0; mt < 2; mt++)
#pragma unroll
        for (int n8 = 0; n8 < 6; n8++) {
            const int gn  = nb * 192 + wn + n8 * 8 + tc;
            const int mat = gn >> 7;
            const int col = gn & 127;
            const float* bias = (mat == 0) ? bq : (mat == 1) ? bk : bv;
            float* Cp = g_qkv[mat];
            const float b0 = bias[col], b1 = bias[col + 1];
            const int r0 = bm + wm + mt * 16 + tr;
            float2 v0 = {acc[mt][n8][0] + b0, acc[mt][n8][1] + b1};
            float2 v1 = {acc[mt][n8][2] + b0, acc[mt][n8][3] + b1};
            *(float2*)&Cp[(size_t)r0 * DH + col]       = v0;
            *(float2*)&Cp[(size_t)(r0 + 8) * DH + col] = v1;
        }
}

// ---------------- Kernel 2: kv partial reduction ---------------------------
__global__ __launch_bounds__(256) void kv_reduce() {
    const int bh    = blockIdx.x;
    const int chunk = blockIdx.y;
    const int b = bh >> 3, h = bh & 7;
    const float* __restrict__ K = g_qkv[1];
    const float* __restrict__ V = g_qkv[2];

    float acc[Dd];
#pragma unroll
    for (int d = 0; d < Dd; d++) acc[d] = 0.f;

    for (int l = chunk * 1024 + threadIdx.x; l < (chunk + 1) * 1024; l += 256) {
        const size_t base = (size_t)(b * Ll + l) * DH + h * Dd;
        float kx[Dd], vx[Dd];
        const float4* kp = (const float4*)(K + base);
        const float4* vp = (const float4*)(V + base);
#pragma unroll
        for (int q = 0; q < 4; q++) {
            float4 kv4 = kp[q];
            kx[q*4+0] = kv4.x; kx[q*4+1] = kv4.y; kx[q*4+2] = kv4.z; kx[q*4+3] = kv4.w;
            float4 vv4 = vp[q];
            vx[q*4+0] = vv4.x; vx[q*4+1] = vv4.y; vx[q*4+2] = vv4.z; vx[q*4+3] = vv4.w;
        }
        float ss = 0.f;
#pragma unroll
        for (int d = 0; d < Dd; d++) ss += kx[d] * kx[d];
        const float rn = rsqrtf(ss);
#pragma unroll
        for (int d = 0; d < Dd; d++) acc[d] += kx[d] * rn * vx[d];
    }

    __shared__ float red[256][17];
#pragma unroll
    for (int d = 0; d < Dd; d++) red[threadIdx.x][d] = acc[d];
    __syncthreads();
    for (int s = 128; s > 0; s >>= 1) {
        if (threadIdx.x < s) {
#pragma unroll
            for (int d = 0; d < Dd; d++)
                red[threadIdx.x][d] += red[threadIdx.x + s][d];
        }
        __syncthreads();
    }
    if (threadIdx.x < Dd)
        g_kvpart[bh][chunk][threadIdx.x] = red[0][threadIdx.x];
}

// ---------------- Kernel 3: q-normalize * kv, LayerNorm --------------------
__global__ __launch_bounds__(256) void finalize(
    const float* __restrict__ gamma, const float* __restrict__ beta,
    float* __restrict__ out)
{
    const int idx = blockIdx.x * blockDim.x + threadIdx.x;
    const int l = idx & (Ll - 1);
    const int h = (idx >> 12) & 7;
    const int b = idx >> 15;

    const size_t qbase = (size_t)(b * Ll + l) * DH + h * Dd;
    float q[Dd];
    const float4* qp = (const float4*)(g_qkv[0] + qbase);
#pragma unroll
    for (int g = 0; g < 4; g++) {
        float4 v = qp[g];
        q[g*4+0] = v.x; q[g*4+1] = v.y; q[g*4+2] = v.z; q[g*4+3] = v.w;
    }

    const int bh = (b << 3) | h;
    float kv[Dd];
#pragma unroll
    for (int d = 0; d < Dd; d++)
        kv[d] = g_kvpart[bh][0][d] + g_kvpart[bh][1][d]
              + g_kvpart[bh][2][d] + g_kvpart[bh][3][d];

    float ss = 0.f;
#pragma unroll
    for (int d = 0; d < Dd; d++) ss += q[d] * q[d];
    const float rn = rsqrtf(ss);

    float a[Dd];
    float mu = 0.f;
#pragma unroll
    for (int d = 0; d < Dd; d++) { a[d] = q[d] * rn * kv[d]; mu += a[d]; }
    mu *= (1.f / Dd);
    float var = 0.f;
#pragma unroll
    for (int d = 0; d < Dd; d++) { float t = a[d] - mu; var += t * t; }
    var *= (1.f / Dd);
    const float rs = rsqrtf(var + 1e-5f);

    float* op = out + (size_t)idx * Dd;
#pragma unroll
    for (int g = 0; g < 4; g++) {
        float4 o;
        o.x = (a[g*4+0] - mu) * rs * gamma[g*4+0] + beta[g*4+0];
        o.y = (a[g*4+1] - mu) * rs * gamma[g*4+1] + beta[g*4+1];
        o.z = (a[g*4+2] - mu) * rs * gamma[g*4+2] + beta[g*4+2];
        o.w = (a[g*4+3] - mu) * rs * gamma[g*4+3] + beta[g*4+3];
        *(float4*)&op[g * 4] = o;
    }
}

// ---------------------------------------------------------------------------
extern "C" void kernel_launch(void* const* d_in, const int* in_sizes, int n_in,
                              void* d_out, int out_size)
{
    (void)in_sizes; (void)n_in; (void)out_size;
    const float* x     = (const float*)d_in[0];
    const float* Wq    = (const float*)d_in[1];
    const float* bq    = (const float*)d_in[2];
    const float* Wk    = (const float*)d_in[3];
    const float* bk    = (const float*)d_in[4];
    const float* Wv    = (const float*)d_in[5];
    const float* bv    = (const float*)d_in[6];
    const float* gamma = (const float*)d_in[7];
    const float* beta  = (const float*)d_in[8];
    float* out = (float*)d_out;

    static bool attr_set = false;
    if (!attr_set) {
        cudaFuncSetAttribute(qkv_gemm_fused,
                             cudaFuncAttributeMaxDynamicSharedMemorySize, GEMM_SMEM);
        attr_set = true;
    }

    qkv_gemm_fused<<<dim3(2, 256), NTHR, GEMM_SMEM>>>(x, Wq, bq, Wk, bk, Wv, bv);
    kv_reduce<<<dim3(Bb * NH, 4), 256>>>();
    finalize<<<(Bb * NH * Ll) / 256, 256>>>(gamma, beta, out);
}